// round 2
// baseline (speedup 1.0000x reference)
#include <cuda_runtime.h>
#include <cuda_bf16.h>
#include <math.h>

// ---------------- problem constants ----------------
#define BATCH    2
#define LQ       8192
#define DM       256
#define DFFN     1024
#define NHEADS   8
#define NLEV     4
#define NPTS     4
#define DHEAD    32
#define STOT     21760           // 128*128 + 64*64 + 32*32 + 16*16
#define ROWS     (BATCH*LQ)      // 16384
#define MVAL     (BATCH*STOT)    // 43520

// ---------------- device scratch (allocation-free) ----------------
__device__ float g_q   [ROWS * DM];      // q = tgt+pos, later reused as x_pre (out-proj + tgt)
__device__ float g_val [MVAL * DM];      // value = src@Wv + bv
__device__ float g_off [ROWS * DM];      // sampling offsets, later reused as ffn residual sum
__device__ float g_att [ROWS * (NHEADS*NLEV*NPTS)]; // attn logits
__device__ float g_smp [ROWS * DM];      // sampled attention output (pre W_out)
__device__ float g_x   [ROWS * DM];      // after LN1
__device__ float g_h   [ROWS * DFFN];    // ffn hidden

// ---------------- elementwise add (float4) ----------------
__global__ void add_kernel(const float* __restrict__ a, const float* __restrict__ b,
                           float* __restrict__ o, int n4) {
    int i = blockIdx.x * blockDim.x + threadIdx.x;
    if (i < n4) {
        float4 x = ((const float4*)a)[i];
        float4 y = ((const float4*)b)[i];
        x.x += y.x; x.y += y.y; x.z += y.z; x.w += y.w;
        ((float4*)o)[i] = x;
    }
}

// ---------------- SGEMM: C = op(A@B + bias [+ res]) ----------------
// A: (M,K) row-major, B: (K,N) row-major, C: (M,N).
// MODE 0: +bias   MODE 1: relu(+bias)   MODE 2: +bias+res
// M,N assumed multiples of 64, K multiple of 16 (true for all our shapes).
template<int MODE>
__global__ void sgemm_kernel(const float* __restrict__ A, const float* __restrict__ B,
                             const float* __restrict__ bias, const float* __restrict__ res,
                             float* __restrict__ C, int M, int N, int K) {
    __shared__ float As[64][17];   // [m][k], padded
    __shared__ float Bs[16][64];   // [k][n]

    const int tid = threadIdx.x;
    const int tx  = tid & 15;      // 0..15 -> col group
    const int ty  = tid >> 4;      // 0..15 -> row group
    const int row0 = blockIdx.y * 64 + ty * 4;
    const int col0 = blockIdx.x * 64 + tx * 4;

    const int la_k = tid & 15;     // A load: k within tile
    const int la_m = tid >> 4;     // A load: base m (stride 16)
    const int lb_n = tid & 63;     // B load: n
    const int lb_k = tid >> 6;     // B load: base k (stride 4)

    float acc[4][4];
#pragma unroll
    for (int i = 0; i < 4; i++)
#pragma unroll
        for (int j = 0; j < 4; j++) acc[i][j] = 0.f;

    for (int k0 = 0; k0 < K; k0 += 16) {
#pragma unroll
        for (int i = 0; i < 4; i++) {
            int m = blockIdx.y * 64 + la_m + i * 16;
            As[la_m + i * 16][la_k] = A[(size_t)m * K + k0 + la_k];
        }
#pragma unroll
        for (int i = 0; i < 4; i++) {
            Bs[lb_k + i * 4][lb_n] = B[(size_t)(k0 + lb_k + i * 4) * N + blockIdx.x * 64 + lb_n];
        }
        __syncthreads();
#pragma unroll
        for (int kk = 0; kk < 16; kk++) {
            float a0 = As[ty * 4 + 0][kk];
            float a1 = As[ty * 4 + 1][kk];
            float a2 = As[ty * 4 + 2][kk];
            float a3 = As[ty * 4 + 3][kk];
            float4 b4 = *(const float4*)&Bs[kk][tx * 4];
            acc[0][0] += a0 * b4.x; acc[0][1] += a0 * b4.y; acc[0][2] += a0 * b4.z; acc[0][3] += a0 * b4.w;
            acc[1][0] += a1 * b4.x; acc[1][1] += a1 * b4.y; acc[1][2] += a1 * b4.z; acc[1][3] += a1 * b4.w;
            acc[2][0] += a2 * b4.x; acc[2][1] += a2 * b4.y; acc[2][2] += a2 * b4.z; acc[2][3] += a2 * b4.w;
            acc[3][0] += a3 * b4.x; acc[3][1] += a3 * b4.y; acc[3][2] += a3 * b4.z; acc[3][3] += a3 * b4.w;
        }
        __syncthreads();
    }

    float4 bb = *(const float4*)&bias[col0];
#pragma unroll
    for (int i = 0; i < 4; i++) {
        size_t off = (size_t)(row0 + i) * N + col0;
        float4 v;
        v.x = acc[i][0] + bb.x; v.y = acc[i][1] + bb.y;
        v.z = acc[i][2] + bb.z; v.w = acc[i][3] + bb.w;
        if (MODE == 1) {
            v.x = fmaxf(v.x, 0.f); v.y = fmaxf(v.y, 0.f);
            v.z = fmaxf(v.z, 0.f); v.w = fmaxf(v.w, 0.f);
        }
        if (MODE == 2) {
            float4 r = *(const float4*)&res[off];
            v.x += r.x; v.y += r.y; v.z += r.z; v.w += r.w;
        }
        *(float4*)&C[off] = v;
    }
}

// ---------------- deformable sampling ----------------
// one warp per (b, q, h); lane = head-dim channel
__global__ void sample_kernel(const float* __restrict__ value,   // (B*S, 256): row b*S+s, col h*32+d
                              const float* __restrict__ offp_g,  // (ROWS, 256)
                              const float* __restrict__ attn_g,  // (ROWS, 128) logits
                              const float* __restrict__ refp,    // (B, LQ, 4, 2)
                              float* __restrict__ out)           // (ROWS, 256)
{
    const int gw   = blockIdx.x * (blockDim.x >> 5) + (threadIdx.x >> 5);
    const int lane = threadIdx.x & 31;
    const int h    = gw & 7;
    const int row  = gw >> 3;            // b*LQ + q
    if (row >= ROWS) return;
    const int b = row / LQ;

    const int HH[NLEV]    = {128, 64, 32, 16};
    const int WW[NLEV]    = {128, 64, 32, 16};
    const int START[NLEV] = {0, 16384, 20480, 21504};

    // softmax over the 16 (level,point) logits, computed redundantly per lane
    const float* ap = attn_g + (size_t)row * 128 + h * 16;
    float lg[16];
#pragma unroll
    for (int j = 0; j < 16; j++) lg[j] = ap[j];
    float mx = lg[0];
#pragma unroll
    for (int j = 1; j < 16; j++) mx = fmaxf(mx, lg[j]);
    float s = 0.f;
#pragma unroll
    for (int j = 0; j < 16; j++) { lg[j] = __expf(lg[j] - mx); s += lg[j]; }
    const float inv = 1.f / s;

    const float* offp = offp_g + (size_t)row * 256 + h * 32;
    const float* rp   = refp + (size_t)row * (NLEV * 2);

    float acc = 0.f;
#pragma unroll
    for (int l = 0; l < NLEV; l++) {
        const int Hl = HH[l], Wl = WW[l];
        const float rx = rp[l * 2 + 0] * (float)Wl;
        const float ry = rp[l * 2 + 1] * (float)Hl;
        const float* vbase = value + ((size_t)(b * STOT + START[l])) * 256 + h * 32 + lane;
#pragma unroll
        for (int p = 0; p < NPTS; p++) {
            const float x = rx + offp[l * 8 + p * 2 + 0] - 0.5f;
            const float y = ry + offp[l * 8 + p * 2 + 1] - 0.5f;
            const float x0f = floorf(x), y0f = floorf(y);
            const float wx = x - x0f, wy = y - y0f;
            const int x0 = (int)x0f, y0 = (int)y0f;
            const float aw = lg[l * 4 + p] * inv;

            const float w00 = (1.f - wx) * (1.f - wy) * aw;
            const float w10 = wx * (1.f - wy) * aw;
            const float w01 = (1.f - wx) * wy * aw;
            const float w11 = wx * wy * aw;

            if (x0     >= 0 && x0     < Wl && y0     >= 0 && y0     < Hl)
                acc += w00 * vbase[(size_t)(y0 * Wl + x0) * 256];
            if (x0 + 1 >= 0 && x0 + 1 < Wl && y0     >= 0 && y0     < Hl)
                acc += w10 * vbase[(size_t)(y0 * Wl + x0 + 1) * 256];
            if (x0     >= 0 && x0     < Wl && y0 + 1 >= 0 && y0 + 1 < Hl)
                acc += w01 * vbase[(size_t)((y0 + 1) * Wl + x0) * 256];
            if (x0 + 1 >= 0 && x0 + 1 < Wl && y0 + 1 >= 0 && y0 + 1 < Hl)
                acc += w11 * vbase[(size_t)((y0 + 1) * Wl + x0 + 1) * 256];
        }
    }
    out[(size_t)row * 256 + h * 32 + lane] = acc;
}

// ---------------- layernorm: warp per 256-elem row ----------------
__global__ void ln_kernel(const float* __restrict__ in, const float* __restrict__ gam,
                          const float* __restrict__ bet, float* __restrict__ out, int rows) {
    const int warp = (blockIdx.x * blockDim.x + threadIdx.x) >> 5;
    const int lane = threadIdx.x & 31;
    if (warp >= rows) return;
    const float* x = in + (size_t)warp * 256 + lane * 8;
    float4 v0 = *(const float4*)(x);
    float4 v1 = *(const float4*)(x + 4);
    float s  = v0.x + v0.y + v0.z + v0.w + v1.x + v1.y + v1.z + v1.w;
    float ss = v0.x*v0.x + v0.y*v0.y + v0.z*v0.z + v0.w*v0.w
             + v1.x*v1.x + v1.y*v1.y + v1.z*v1.z + v1.w*v1.w;
#pragma unroll
    for (int o = 16; o > 0; o >>= 1) {
        s  += __shfl_xor_sync(0xffffffffu, s,  o);
        ss += __shfl_xor_sync(0xffffffffu, ss, o);
    }
    const float mu  = s * (1.f / 256.f);
    const float var = ss * (1.f / 256.f) - mu * mu;
    const float inv = rsqrtf(var + 1e-5f);

    float4 g0 = *(const float4*)(gam + lane * 8);
    float4 g1 = *(const float4*)(gam + lane * 8 + 4);
    float4 b0 = *(const float4*)(bet + lane * 8);
    float4 b1 = *(const float4*)(bet + lane * 8 + 4);
    float4 o0, o1;
    o0.x = (v0.x - mu) * inv * g0.x + b0.x;
    o0.y = (v0.y - mu) * inv * g0.y + b0.y;
    o0.z = (v0.z - mu) * inv * g0.z + b0.z;
    o0.w = (v0.w - mu) * inv * g0.w + b0.w;
    o1.x = (v1.x - mu) * inv * g1.x + b1.x;
    o1.y = (v1.y - mu) * inv * g1.y + b1.y;
    o1.z = (v1.z - mu) * inv * g1.z + b1.z;
    o1.w = (v1.w - mu) * inv * g1.w + b1.w;
    float* y = out + (size_t)warp * 256 + lane * 8;
    *(float4*)(y)     = o0;
    *(float4*)(y + 4) = o1;
}

// ---------------- host launcher ----------------
extern "C" void kernel_launch(void* const* d_in, const int* in_sizes, int n_in,
                              void* d_out, int out_size) {
    const float* tgt   = (const float*)d_in[0];
    const float* qpos  = (const float*)d_in[1];
    const float* refp  = (const float*)d_in[2];
    const float* src   = (const float*)d_in[3];
    // d_in[4] spatial_shapes (int64), d_in[5] level_start_index (int64): compile-time constants
    const float* Wv    = (const float*)d_in[6];
    const float* bv    = (const float*)d_in[7];
    const float* Woff  = (const float*)d_in[8];
    const float* boff  = (const float*)d_in[9];
    const float* Wat   = (const float*)d_in[10];
    const float* bat   = (const float*)d_in[11];
    const float* Wout  = (const float*)d_in[12];
    const float* bout  = (const float*)d_in[13];
    const float* ln1g  = (const float*)d_in[14];
    const float* ln1b  = (const float*)d_in[15];
    const float* W1    = (const float*)d_in[16];
    const float* b1    = (const float*)d_in[17];
    const float* W2    = (const float*)d_in[18];
    const float* b2    = (const float*)d_in[19];
    const float* ln3g  = (const float*)d_in[20];
    const float* ln3b  = (const float*)d_in[21];
    float* out = (float*)d_out;

    float *p_q, *p_val, *p_off, *p_att, *p_smp, *p_x, *p_h;
    cudaGetSymbolAddress((void**)&p_q,   g_q);
    cudaGetSymbolAddress((void**)&p_val, g_val);
    cudaGetSymbolAddress((void**)&p_off, g_off);
    cudaGetSymbolAddress((void**)&p_att, g_att);
    cudaGetSymbolAddress((void**)&p_smp, g_smp);
    cudaGetSymbolAddress((void**)&p_x,   g_x);
    cudaGetSymbolAddress((void**)&p_h,   g_h);

    // 1. q = tgt + query_pos
    {
        int n4 = ROWS * DM / 4;
        add_kernel<<<(n4 + 255) / 256, 256>>>(tgt, qpos, p_q, n4);
    }
    // 2. value = src @ Wv + bv        (43520 x 256 x 256)
    sgemm_kernel<0><<<dim3(DM / 64, MVAL / 64), 256>>>(src, Wv, bv, nullptr, p_val, MVAL, DM, DM);
    // 3. off = q @ Woff + boff        (16384 x 256 x 256)
    sgemm_kernel<0><<<dim3(DM / 64, ROWS / 64), 256>>>(p_q, Woff, boff, nullptr, p_off, ROWS, DM, DM);
    // 4. attn logits = q @ Wat + bat  (16384 x 128 x 256)
    sgemm_kernel<0><<<dim3(128 / 64, ROWS / 64), 256>>>(p_q, Wat, bat, nullptr, p_att, ROWS, 128, DM);
    // 5. deformable sampling -> g_smp
    {
        int nwarps = ROWS * NHEADS;           // 131072
        sample_kernel<<<nwarps / 8, 256>>>(p_val, p_off, p_att, refp, p_smp);
    }
    // 6. x_pre = smp @ Wout + bout + tgt  (reuse g_q)
    sgemm_kernel<2><<<dim3(DM / 64, ROWS / 64), 256>>>(p_smp, Wout, bout, tgt, p_q, ROWS, DM, DM);
    // 7. x = LN1(x_pre)
    ln_kernel<<<ROWS / 8, 256>>>(p_q, ln1g, ln1b, p_x, ROWS);
    // 8. h = relu(x @ W1 + b1)        (16384 x 1024 x 256)
    sgemm_kernel<1><<<dim3(DFFN / 64, ROWS / 64), 256>>>(p_x, W1, b1, nullptr, p_h, ROWS, DFFN, DM);
    // 9. y_pre = h @ W2 + b2 + x      (16384 x 256 x 1024, reuse g_off)
    sgemm_kernel<2><<<dim3(DM / 64, ROWS / 64), 256>>>(p_h, W2, b2, p_x, p_off, ROWS, DM, DFFN);
    // 10. out = LN3(y_pre)
    ln_kernel<<<ROWS / 8, 256>>>(p_off, ln3g, ln3b, out, ROWS);
}

// round 3
// speedup vs baseline: 1.9724x; 1.9724x over previous
#include <cuda_runtime.h>
#include <cuda_bf16.h>
#include <math.h>

// ---------------- problem constants ----------------
#define BATCH    2
#define LQ       8192
#define DM       256
#define DFFN     1024
#define NHEADS   8
#define NLEV     4
#define NPTS     4
#define DHEAD    32
#define STOT     21760           // 128*128 + 64*64 + 32*32 + 16*16
#define ROWS     (BATCH*LQ)      // 16384
#define MVAL     (BATCH*STOT)    // 43520

// ---------------- device scratch (allocation-free) ----------------
__device__ float g_q   [ROWS * DM];
__device__ float g_val [MVAL * DM];
__device__ float g_off [ROWS * DM];
__device__ float g_att [ROWS * (NHEADS*NLEV*NPTS)];
__device__ float g_smp [ROWS * DM];
__device__ float g_x   [ROWS * DM];
__device__ float g_h   [ROWS * DFFN];

// ---------------- elementwise add (float4) ----------------
__global__ void add_kernel(const float* __restrict__ a, const float* __restrict__ b,
                           float* __restrict__ o, int n4) {
    int i = blockIdx.x * blockDim.x + threadIdx.x;
    if (i < n4) {
        float4 x = ((const float4*)a)[i];
        float4 y = ((const float4*)b)[i];
        x.x += y.x; x.y += y.y; x.z += y.z; x.w += y.w;
        ((float4*)o)[i] = x;
    }
}

// ---------------- high-throughput SGEMM ----------------
// C = op(A@B + bias [+ res]); A:(M,K) row-major, B:(K,N) row-major.
// 128x128x16 tiles, 256 threads, 8x8 per thread (4x 4x4 quadrants),
// cp.async double-buffered. M%128==0, N%128==0, K%16==0 (true for all shapes).
#define BM 128
#define BN 128
#define BK 16

template<int MODE>
__global__ __launch_bounds__(256, 2)
void sgemm_kernel(const float* __restrict__ A, const float* __restrict__ B,
                  const float* __restrict__ bias, const float* __restrict__ res,
                  float* __restrict__ C, int M, int N, int K) {
    __shared__ float As[2][BM][BK];   // [m][k] — compute reads scalar column (broadcast)
    __shared__ float Bs[2][BK][BN];   // [k][n] — compute reads float4

    const int tid = threadIdx.x;
    const int tx  = tid & 15;         // 0..15
    const int ty  = tid >> 4;         // 0..15
    const int bm0 = blockIdx.y * BM;
    const int bn0 = blockIdx.x * BN;

    // loader mappings
    const int am = tid >> 1;          // 0..127 (A row within tile)
    const int ak = (tid & 1) * 8;     // 0 or 8 (two float4s: +0, +4)
    const int bk = tid >> 4;          // 0..15  (B row within tile)
    const int bn = (tid & 15) * 8;    // two float4s: +0, +4

    const float* Ag = A + (size_t)(bm0 + am) * K + ak;
    const float* Bg = B + (size_t)bk * N + bn0 + bn;

    unsigned sA0 = (unsigned)__cvta_generic_to_shared(&As[0][am][ak]);
    unsigned sA1 = (unsigned)__cvta_generic_to_shared(&As[1][am][ak]);
    unsigned sB0 = (unsigned)__cvta_generic_to_shared(&Bs[0][bk][bn]);
    unsigned sB1 = (unsigned)__cvta_generic_to_shared(&Bs[1][bk][bn]);

    float acc[2][2][4][4];
#pragma unroll
    for (int qr = 0; qr < 2; qr++)
#pragma unroll
        for (int qc = 0; qc < 2; qc++)
#pragma unroll
            for (int i = 0; i < 4; i++)
#pragma unroll
                for (int j = 0; j < 4; j++) acc[qr][qc][i][j] = 0.f;

    const int T = K / BK;

#define LOAD_TILE(SA, SB, K0)                                                        \
    {                                                                                \
        const float* a_ = Ag + (K0);                                                 \
        asm volatile("cp.async.cg.shared.global [%0], [%1], 16;\n"                   \
                     :: "r"(SA), "l"(a_));                                           \
        asm volatile("cp.async.cg.shared.global [%0], [%1], 16;\n"                   \
                     :: "r"((SA) + 16), "l"(a_ + 4));                                \
        const float* b_ = Bg + (size_t)(K0) * N;                                     \
        asm volatile("cp.async.cg.shared.global [%0], [%1], 16;\n"                   \
                     :: "r"(SB), "l"(b_));                                           \
        asm volatile("cp.async.cg.shared.global [%0], [%1], 16;\n"                   \
                     :: "r"((SB) + 16), "l"(b_ + 4));                                \
        asm volatile("cp.async.commit_group;\n");                                    \
    }

    LOAD_TILE(sA0, sB0, 0);

    for (int t = 0; t < T; t++) {
        const int buf = t & 1;
        if (t + 1 < T) {
            if (buf == 0) { LOAD_TILE(sA1, sB1, (t + 1) * BK); }
            else          { LOAD_TILE(sA0, sB0, (t + 1) * BK); }
            asm volatile("cp.async.wait_group 1;\n" ::: "memory");
        } else {
            asm volatile("cp.async.wait_group 0;\n" ::: "memory");
        }
        __syncthreads();

#pragma unroll
        for (int kk = 0; kk < BK; kk++) {
            float a[2][4];
#pragma unroll
            for (int qr = 0; qr < 2; qr++)
#pragma unroll
                for (int i = 0; i < 4; i++)
                    a[qr][i] = As[buf][qr * 64 + ty * 4 + i][kk];
            float4 b0 = *(const float4*)&Bs[buf][kk][tx * 4];
            float4 b1 = *(const float4*)&Bs[buf][kk][64 + tx * 4];
#pragma unroll
            for (int qr = 0; qr < 2; qr++)
#pragma unroll
                for (int i = 0; i < 4; i++) {
                    float av = a[qr][i];
                    acc[qr][0][i][0] += av * b0.x;
                    acc[qr][0][i][1] += av * b0.y;
                    acc[qr][0][i][2] += av * b0.z;
                    acc[qr][0][i][3] += av * b0.w;
                    acc[qr][1][i][0] += av * b1.x;
                    acc[qr][1][i][1] += av * b1.y;
                    acc[qr][1][i][2] += av * b1.z;
                    acc[qr][1][i][3] += av * b1.w;
                }
        }
        __syncthreads();
    }
#undef LOAD_TILE

    // epilogue
    float4 bb[2];
    bb[0] = *(const float4*)&bias[bn0 + tx * 4];
    bb[1] = *(const float4*)&bias[bn0 + 64 + tx * 4];
#pragma unroll
    for (int qr = 0; qr < 2; qr++) {
#pragma unroll
        for (int i = 0; i < 4; i++) {
            const int row = bm0 + qr * 64 + ty * 4 + i;
#pragma unroll
            for (int qc = 0; qc < 2; qc++) {
                const size_t off = (size_t)row * N + bn0 + qc * 64 + tx * 4;
                float4 v;
                v.x = acc[qr][qc][i][0] + bb[qc].x;
                v.y = acc[qr][qc][i][1] + bb[qc].y;
                v.z = acc[qr][qc][i][2] + bb[qc].z;
                v.w = acc[qr][qc][i][3] + bb[qc].w;
                if (MODE == 1) {
                    v.x = fmaxf(v.x, 0.f); v.y = fmaxf(v.y, 0.f);
                    v.z = fmaxf(v.z, 0.f); v.w = fmaxf(v.w, 0.f);
                }
                if (MODE == 2) {
                    float4 r = *(const float4*)&res[off];
                    v.x += r.x; v.y += r.y; v.z += r.z; v.w += r.w;
                }
                *(float4*)&C[off] = v;
            }
        }
    }
}

// ---------------- deformable sampling ----------------
// one warp per (b, q, h); lane = head-dim channel
__global__ void sample_kernel(const float* __restrict__ value,   // (B*S, 256)
                              const float* __restrict__ offp_g,  // (ROWS, 256)
                              const float* __restrict__ attn_g,  // (ROWS, 128) logits
                              const float* __restrict__ refp,    // (B, LQ, 4, 2)
                              float* __restrict__ out)           // (ROWS, 256)
{
    const int gw   = blockIdx.x * (blockDim.x >> 5) + (threadIdx.x >> 5);
    const int lane = threadIdx.x & 31;
    const int h    = gw & 7;
    const int row  = gw >> 3;            // b*LQ + q
    if (row >= ROWS) return;
    const int b = row / LQ;

    const int HH[NLEV]    = {128, 64, 32, 16};
    const int WW[NLEV]    = {128, 64, 32, 16};
    const int START[NLEV] = {0, 16384, 20480, 21504};

    const float* ap = attn_g + (size_t)row * 128 + h * 16;
    float lg[16];
#pragma unroll
    for (int j = 0; j < 16; j++) lg[j] = ap[j];
    float mx = lg[0];
#pragma unroll
    for (int j = 1; j < 16; j++) mx = fmaxf(mx, lg[j]);
    float s = 0.f;
#pragma unroll
    for (int j = 0; j < 16; j++) { lg[j] = __expf(lg[j] - mx); s += lg[j]; }
    const float inv = 1.f / s;

    const float* offp = offp_g + (size_t)row * 256 + h * 32;
    const float* rp   = refp + (size_t)row * (NLEV * 2);

    float acc = 0.f;
#pragma unroll
    for (int l = 0; l < NLEV; l++) {
        const int Hl = HH[l], Wl = WW[l];
        const float rx = rp[l * 2 + 0] * (float)Wl;
        const float ry = rp[l * 2 + 1] * (float)Hl;
        const float* vbase = value + ((size_t)(b * STOT + START[l])) * 256 + h * 32 + lane;
#pragma unroll
        for (int p = 0; p < NPTS; p++) {
            const float x = rx + offp[l * 8 + p * 2 + 0] - 0.5f;
            const float y = ry + offp[l * 8 + p * 2 + 1] - 0.5f;
            const float x0f = floorf(x), y0f = floorf(y);
            const float wx = x - x0f, wy = y - y0f;
            const int x0 = (int)x0f, y0 = (int)y0f;
            const float aw = lg[l * 4 + p] * inv;

            const float w00 = (1.f - wx) * (1.f - wy) * aw;
            const float w10 = wx * (1.f - wy) * aw;
            const float w01 = (1.f - wx) * wy * aw;
            const float w11 = wx * wy * aw;

            if (x0     >= 0 && x0     < Wl && y0     >= 0 && y0     < Hl)
                acc += w00 * vbase[(size_t)(y0 * Wl + x0) * 256];
            if (x0 + 1 >= 0 && x0 + 1 < Wl && y0     >= 0 && y0     < Hl)
                acc += w10 * vbase[(size_t)(y0 * Wl + x0 + 1) * 256];
            if (x0     >= 0 && x0     < Wl && y0 + 1 >= 0 && y0 + 1 < Hl)
                acc += w01 * vbase[(size_t)((y0 + 1) * Wl + x0) * 256];
            if (x0 + 1 >= 0 && x0 + 1 < Wl && y0 + 1 >= 0 && y0 + 1 < Hl)
                acc += w11 * vbase[(size_t)((y0 + 1) * Wl + x0 + 1) * 256];
        }
    }
    out[(size_t)row * 256 + h * 32 + lane] = acc;
}

// ---------------- layernorm: warp per 256-elem row ----------------
__global__ void ln_kernel(const float* __restrict__ in, const float* __restrict__ gam,
                          const float* __restrict__ bet, float* __restrict__ out, int rows) {
    const int warp = (blockIdx.x * blockDim.x + threadIdx.x) >> 5;
    const int lane = threadIdx.x & 31;
    if (warp >= rows) return;
    const float* x = in + (size_t)warp * 256 + lane * 8;
    float4 v0 = *(const float4*)(x);
    float4 v1 = *(const float4*)(x + 4);
    float s  = v0.x + v0.y + v0.z + v0.w + v1.x + v1.y + v1.z + v1.w;
    float ss = v0.x*v0.x + v0.y*v0.y + v0.z*v0.z + v0.w*v0.w
             + v1.x*v1.x + v1.y*v1.y + v1.z*v1.z + v1.w*v1.w;
#pragma unroll
    for (int o = 16; o > 0; o >>= 1) {
        s  += __shfl_xor_sync(0xffffffffu, s,  o);
        ss += __shfl_xor_sync(0xffffffffu, ss, o);
    }
    const float mu  = s * (1.f / 256.f);
    const float var = ss * (1.f / 256.f) - mu * mu;
    const float inv = rsqrtf(var + 1e-5f);

    float4 g0 = *(const float4*)(gam + lane * 8);
    float4 g1 = *(const float4*)(gam + lane * 8 + 4);
    float4 b0 = *(const float4*)(bet + lane * 8);
    float4 b1 = *(const float4*)(bet + lane * 8 + 4);
    float4 o0, o1;
    o0.x = (v0.x - mu) * inv * g0.x + b0.x;
    o0.y = (v0.y - mu) * inv * g0.y + b0.y;
    o0.z = (v0.z - mu) * inv * g0.z + b0.z;
    o0.w = (v0.w - mu) * inv * g0.w + b0.w;
    o1.x = (v1.x - mu) * inv * g1.x + b1.x;
    o1.y = (v1.y - mu) * inv * g1.y + b1.y;
    o1.z = (v1.z - mu) * inv * g1.z + b1.z;
    o1.w = (v1.w - mu) * inv * g1.w + b1.w;
    float* y = out + (size_t)warp * 256 + lane * 8;
    *(float4*)(y)     = o0;
    *(float4*)(y + 4) = o1;
}

// ---------------- host launcher ----------------
extern "C" void kernel_launch(void* const* d_in, const int* in_sizes, int n_in,
                              void* d_out, int out_size) {
    const float* tgt   = (const float*)d_in[0];
    const float* qpos  = (const float*)d_in[1];
    const float* refp  = (const float*)d_in[2];
    const float* src   = (const float*)d_in[3];
    const float* Wv    = (const float*)d_in[6];
    const float* bv    = (const float*)d_in[7];
    const float* Woff  = (const float*)d_in[8];
    const float* boff  = (const float*)d_in[9];
    const float* Wat   = (const float*)d_in[10];
    const float* bat   = (const float*)d_in[11];
    const float* Wout  = (const float*)d_in[12];
    const float* bout  = (const float*)d_in[13];
    const float* ln1g  = (const float*)d_in[14];
    const float* ln1b  = (const float*)d_in[15];
    const float* W1    = (const float*)d_in[16];
    const float* b1    = (const float*)d_in[17];
    const float* W2    = (const float*)d_in[18];
    const float* b2    = (const float*)d_in[19];
    const float* ln3g  = (const float*)d_in[20];
    const float* ln3b  = (const float*)d_in[21];
    float* out = (float*)d_out;

    float *p_q, *p_val, *p_off, *p_att, *p_smp, *p_x, *p_h;
    cudaGetSymbolAddress((void**)&p_q,   g_q);
    cudaGetSymbolAddress((void**)&p_val, g_val);
    cudaGetSymbolAddress((void**)&p_off, g_off);
    cudaGetSymbolAddress((void**)&p_att, g_att);
    cudaGetSymbolAddress((void**)&p_smp, g_smp);
    cudaGetSymbolAddress((void**)&p_x,   g_x);
    cudaGetSymbolAddress((void**)&p_h,   g_h);

    // 1. q = tgt + query_pos
    {
        int n4 = ROWS * DM / 4;
        add_kernel<<<(n4 + 255) / 256, 256>>>(tgt, qpos, p_q, n4);
    }
    // 2. value = src @ Wv + bv        (43520 x 256 x 256)
    sgemm_kernel<0><<<dim3(DM / BN, MVAL / BM), 256>>>(src, Wv, bv, nullptr, p_val, MVAL, DM, DM);
    // 3. off = q @ Woff + boff        (16384 x 256 x 256)
    sgemm_kernel<0><<<dim3(DM / BN, ROWS / BM), 256>>>(p_q, Woff, boff, nullptr, p_off, ROWS, DM, DM);
    // 4. attn logits = q @ Wat + bat  (16384 x 128 x 256)
    sgemm_kernel<0><<<dim3(128 / BN, ROWS / BM), 256>>>(p_q, Wat, bat, nullptr, p_att, ROWS, 128, DM);
    // 5. deformable sampling -> g_smp
    {
        int nwarps = ROWS * NHEADS;           // 131072
        sample_kernel<<<nwarps / 8, 256>>>(p_val, p_off, p_att, refp, p_smp);
    }
    // 6. x_pre = smp @ Wout + bout + tgt  (reuse g_q)
    sgemm_kernel<2><<<dim3(DM / BN, ROWS / BM), 256>>>(p_smp, Wout, bout, tgt, p_q, ROWS, DM, DM);
    // 7. x = LN1(x_pre)
    ln_kernel<<<ROWS / 8, 256>>>(p_q, ln1g, ln1b, p_x, ROWS);
    // 8. h = relu(x @ W1 + b1)        (16384 x 1024 x 256)
    sgemm_kernel<1><<<dim3(DFFN / BN, ROWS / BM), 256>>>(p_x, W1, b1, nullptr, p_h, ROWS, DFFN, DM);
    // 9. y_pre = h @ W2 + b2 + x      (16384 x 256 x 1024, reuse g_off)
    sgemm_kernel<2><<<dim3(DM / BN, ROWS / BM), 256>>>(p_h, W2, b2, p_x, p_off, ROWS, DM, DFFN);
    // 10. out = LN3(y_pre)
    ln_kernel<<<ROWS / 8, 256>>>(p_off, ln3g, ln3b, out, ROWS);
}

// round 4
// speedup vs baseline: 1.9775x; 1.0026x over previous
#include <cuda_runtime.h>
#include <cuda_bf16.h>
#include <math.h>

// ---------------- problem constants ----------------
#define BATCH    2
#define LQ       8192
#define DM       256
#define DFFN     1024
#define NHEADS   8
#define NLEV     4
#define NPTS     4
#define DHEAD    32
#define STOT     21760           // 128*128 + 64*64 + 32*32 + 16*16
#define ROWS     (BATCH*LQ)      // 16384
#define MVAL     (BATCH*STOT)    // 43520

// ---------------- device scratch (allocation-free) ----------------
__device__ float g_q   [ROWS * DM];
__device__ float g_val [MVAL * DM];
__device__ float g_off [ROWS * DM];
__device__ float g_att [ROWS * (NHEADS*NLEV*NPTS)];
__device__ float g_smp [ROWS * DM];
__device__ float g_x   [ROWS * DM];
__device__ float g_h   [ROWS * DFFN];

// ---------------- f32x2 packed helpers (Blackwell FFMA2) ----------------
__device__ __forceinline__ unsigned long long pack2_dup(float v) {
    unsigned long long r;
    asm("mov.b64 %0, {%1, %1};" : "=l"(r) : "f"(v));
    return r;
}
__device__ __forceinline__ void ffma2(unsigned long long& d,
                                      unsigned long long a,
                                      unsigned long long b) {
    asm("fma.rn.f32x2 %0, %1, %2, %0;" : "+l"(d) : "l"(a), "l"(b));
}
__device__ __forceinline__ float2 unpack2(unsigned long long v) {
    float2 r;
    asm("mov.b64 {%0, %1}, %2;" : "=f"(r.x), "=f"(r.y) : "l"(v));
    return r;
}

// ---------------- elementwise add (float4) ----------------
__global__ void add_kernel(const float* __restrict__ a, const float* __restrict__ b,
                           float* __restrict__ o, int n4) {
    int i = blockIdx.x * blockDim.x + threadIdx.x;
    if (i < n4) {
        float4 x = ((const float4*)a)[i];
        float4 y = ((const float4*)b)[i];
        x.x += y.x; x.y += y.y; x.z += y.z; x.w += y.w;
        ((float4*)o)[i] = x;
    }
}

// ---------------- high-throughput SGEMM (packed f32x2 math) ----------------
// C = op(A@B + bias [+ res]); A:(M,K) row-major, B:(K,N) row-major.
// 128x128x16 tiles, 256 threads, 8x8 per thread (4x 4x4 quadrants),
// cp.async double-buffered. M%128==0, N%128==0, K%16==0 (true for all shapes).
#define BM 128
#define BN 128
#define BK 16

template<int MODE>
__global__ __launch_bounds__(256, 2)
void sgemm_kernel(const float* __restrict__ A, const float* __restrict__ B,
                  const float* __restrict__ bias, const float* __restrict__ res,
                  float* __restrict__ C, int M, int N, int K) {
    __shared__ float As[2][BM][BK];   // [m][k] — compute reads scalar column (broadcast)
    __shared__ float Bs[2][BK][BN];   // [k][n] — compute reads 16B (2x packed f32x2)

    const int tid = threadIdx.x;
    const int tx  = tid & 15;         // 0..15
    const int ty  = tid >> 4;         // 0..15
    const int bm0 = blockIdx.y * BM;
    const int bn0 = blockIdx.x * BN;

    // loader mappings
    const int am = tid >> 1;          // 0..127 (A row within tile)
    const int ak = (tid & 1) * 8;     // 0 or 8 (two float4s: +0, +4)
    const int bk = tid >> 4;          // 0..15  (B row within tile)
    const int bn = (tid & 15) * 8;    // two float4s: +0, +4

    const float* Ag = A + (size_t)(bm0 + am) * K + ak;
    const float* Bg = B + (size_t)bk * N + bn0 + bn;

    unsigned sA0 = (unsigned)__cvta_generic_to_shared(&As[0][am][ak]);
    unsigned sA1 = (unsigned)__cvta_generic_to_shared(&As[1][am][ak]);
    unsigned sB0 = (unsigned)__cvta_generic_to_shared(&Bs[0][bk][bn]);
    unsigned sB1 = (unsigned)__cvta_generic_to_shared(&Bs[1][bk][bn]);

    // packed accumulators: [qr][qc][i][j2], each u64 = 2 adjacent N columns
    unsigned long long acc[2][2][4][2];
#pragma unroll
    for (int qr = 0; qr < 2; qr++)
#pragma unroll
        for (int qc = 0; qc < 2; qc++)
#pragma unroll
            for (int i = 0; i < 4; i++) {
                acc[qr][qc][i][0] = 0ull;
                acc[qr][qc][i][1] = 0ull;
            }

    const int T = K / BK;

#define LOAD_TILE(SA, SB, K0)                                                        \
    {                                                                                \
        const float* a_ = Ag + (K0);                                                 \
        asm volatile("cp.async.cg.shared.global [%0], [%1], 16;\n"                   \
                     :: "r"(SA), "l"(a_));                                           \
        asm volatile("cp.async.cg.shared.global [%0], [%1], 16;\n"                   \
                     :: "r"((SA) + 16), "l"(a_ + 4));                                \
        const float* b_ = Bg + (size_t)(K0) * N;                                     \
        asm volatile("cp.async.cg.shared.global [%0], [%1], 16;\n"                   \
                     :: "r"(SB), "l"(b_));                                           \
        asm volatile("cp.async.cg.shared.global [%0], [%1], 16;\n"                   \
                     :: "r"((SB) + 16), "l"(b_ + 4));                                \
        asm volatile("cp.async.commit_group;\n");                                    \
    }

    LOAD_TILE(sA0, sB0, 0);

    for (int t = 0; t < T; t++) {
        const int buf = t & 1;
        if (t + 1 < T) {
            if (buf == 0) { LOAD_TILE(sA1, sB1, (t + 1) * BK); }
            else          { LOAD_TILE(sA0, sB0, (t + 1) * BK); }
            asm volatile("cp.async.wait_group 1;\n" ::: "memory");
        } else {
            asm volatile("cp.async.wait_group 0;\n" ::: "memory");
        }
        __syncthreads();

#pragma unroll
        for (int kk = 0; kk < BK; kk++) {
            // A values broadcast-packed into both f32x2 lanes
            unsigned long long a2[2][4];
#pragma unroll
            for (int qr = 0; qr < 2; qr++)
#pragma unroll
                for (int i = 0; i < 4; i++)
                    a2[qr][i] = pack2_dup(As[buf][qr * 64 + ty * 4 + i][kk]);
            // B values: 16B loads reinterpreted as 2 packed f32x2 each
            ulonglong2 b0 = *(const ulonglong2*)&Bs[buf][kk][tx * 4];
            ulonglong2 b1 = *(const ulonglong2*)&Bs[buf][kk][64 + tx * 4];
#pragma unroll
            for (int qr = 0; qr < 2; qr++)
#pragma unroll
                for (int i = 0; i < 4; i++) {
                    unsigned long long av = a2[qr][i];
                    ffma2(acc[qr][0][i][0], av, b0.x);
                    ffma2(acc[qr][0][i][1], av, b0.y);
                    ffma2(acc[qr][1][i][0], av, b1.x);
                    ffma2(acc[qr][1][i][1], av, b1.y);
                }
        }
        __syncthreads();
    }
#undef LOAD_TILE

    // epilogue
    float4 bb[2];
    bb[0] = *(const float4*)&bias[bn0 + tx * 4];
    bb[1] = *(const float4*)&bias[bn0 + 64 + tx * 4];
#pragma unroll
    for (int qr = 0; qr < 2; qr++) {
#pragma unroll
        for (int i = 0; i < 4; i++) {
            const int row = bm0 + qr * 64 + ty * 4 + i;
#pragma unroll
            for (int qc = 0; qc < 2; qc++) {
                const size_t off = (size_t)row * N + bn0 + qc * 64 + tx * 4;
                float2 p0 = unpack2(acc[qr][qc][i][0]);
                float2 p1 = unpack2(acc[qr][qc][i][1]);
                float4 v;
                v.x = p0.x + bb[qc].x;
                v.y = p0.y + bb[qc].y;
                v.z = p1.x + bb[qc].z;
                v.w = p1.y + bb[qc].w;
                if (MODE == 1) {
                    v.x = fmaxf(v.x, 0.f); v.y = fmaxf(v.y, 0.f);
                    v.z = fmaxf(v.z, 0.f); v.w = fmaxf(v.w, 0.f);
                }
                if (MODE == 2) {
                    float4 r = *(const float4*)&res[off];
                    v.x += r.x; v.y += r.y; v.z += r.z; v.w += r.w;
                }
                *(float4*)&C[off] = v;
            }
        }
    }
}

// ---------------- deformable sampling ----------------
// one warp per (b, q, h); lane = head-dim channel
__global__ void sample_kernel(const float* __restrict__ value,   // (B*S, 256)
                              const float* __restrict__ offp_g,  // (ROWS, 256)
                              const float* __restrict__ attn_g,  // (ROWS, 128) logits
                              const float* __restrict__ refp,    // (B, LQ, 4, 2)
                              float* __restrict__ out)           // (ROWS, 256)
{
    const int gw   = blockIdx.x * (blockDim.x >> 5) + (threadIdx.x >> 5);
    const int lane = threadIdx.x & 31;
    const int h    = gw & 7;
    const int row  = gw >> 3;            // b*LQ + q
    if (row >= ROWS) return;
    const int b = row / LQ;

    const int HH[NLEV]    = {128, 64, 32, 16};
    const int WW[NLEV]    = {128, 64, 32, 16};
    const int START[NLEV] = {0, 16384, 20480, 21504};

    const float* ap = attn_g + (size_t)row * 128 + h * 16;
    float lg[16];
#pragma unroll
    for (int j = 0; j < 16; j++) lg[j] = ap[j];
    float mx = lg[0];
#pragma unroll
    for (int j = 1; j < 16; j++) mx = fmaxf(mx, lg[j]);
    float s = 0.f;
#pragma unroll
    for (int j = 0; j < 16; j++) { lg[j] = __expf(lg[j] - mx); s += lg[j]; }
    const float inv = 1.f / s;

    const float* offp = offp_g + (size_t)row * 256 + h * 32;
    const float* rp   = refp + (size_t)row * (NLEV * 2);

    float acc = 0.f;
#pragma unroll
    for (int l = 0; l < NLEV; l++) {
        const int Hl = HH[l], Wl = WW[l];
        const float rx = rp[l * 2 + 0] * (float)Wl;
        const float ry = rp[l * 2 + 1] * (float)Hl;
        const float* vbase = value + ((size_t)(b * STOT + START[l])) * 256 + h * 32 + lane;
#pragma unroll
        for (int p = 0; p < NPTS; p++) {
            const float x = rx + offp[l * 8 + p * 2 + 0] - 0.5f;
            const float y = ry + offp[l * 8 + p * 2 + 1] - 0.5f;
            const float x0f = floorf(x), y0f = floorf(y);
            const float wx = x - x0f, wy = y - y0f;
            const int x0 = (int)x0f, y0 = (int)y0f;
            const float aw = lg[l * 4 + p] * inv;

            const float w00 = (1.f - wx) * (1.f - wy) * aw;
            const float w10 = wx * (1.f - wy) * aw;
            const float w01 = (1.f - wx) * wy * aw;
            const float w11 = wx * wy * aw;

            if (x0     >= 0 && x0     < Wl && y0     >= 0 && y0     < Hl)
                acc += w00 * vbase[(size_t)(y0 * Wl + x0) * 256];
            if (x0 + 1 >= 0 && x0 + 1 < Wl && y0     >= 0 && y0     < Hl)
                acc += w10 * vbase[(size_t)(y0 * Wl + x0 + 1) * 256];
            if (x0     >= 0 && x0     < Wl && y0 + 1 >= 0 && y0 + 1 < Hl)
                acc += w01 * vbase[(size_t)((y0 + 1) * Wl + x0) * 256];
            if (x0 + 1 >= 0 && x0 + 1 < Wl && y0 + 1 >= 0 && y0 + 1 < Hl)
                acc += w11 * vbase[(size_t)((y0 + 1) * Wl + x0 + 1) * 256];
        }
    }
    out[(size_t)row * 256 + h * 32 + lane] = acc;
}

// ---------------- layernorm: warp per 256-elem row ----------------
__global__ void ln_kernel(const float* __restrict__ in, const float* __restrict__ gam,
                          const float* __restrict__ bet, float* __restrict__ out, int rows) {
    const int warp = (blockIdx.x * blockDim.x + threadIdx.x) >> 5;
    const int lane = threadIdx.x & 31;
    if (warp >= rows) return;
    const float* x = in + (size_t)warp * 256 + lane * 8;
    float4 v0 = *(const float4*)(x);
    float4 v1 = *(const float4*)(x + 4);
    float s  = v0.x + v0.y + v0.z + v0.w + v1.x + v1.y + v1.z + v1.w;
    float ss = v0.x*v0.x + v0.y*v0.y + v0.z*v0.z + v0.w*v0.w
             + v1.x*v1.x + v1.y*v1.y + v1.z*v1.z + v1.w*v1.w;
#pragma unroll
    for (int o = 16; o > 0; o >>= 1) {
        s  += __shfl_xor_sync(0xffffffffu, s,  o);
        ss += __shfl_xor_sync(0xffffffffu, ss, o);
    }
    const float mu  = s * (1.f / 256.f);
    const float var = ss * (1.f / 256.f) - mu * mu;
    const float inv = rsqrtf(var + 1e-5f);

    float4 g0 = *(const float4*)(gam + lane * 8);
    float4 g1 = *(const float4*)(gam + lane * 8 + 4);
    float4 b0 = *(const float4*)(bet + lane * 8);
    float4 b1 = *(const float4*)(bet + lane * 8 + 4);
    float4 o0, o1;
    o0.x = (v0.x - mu) * inv * g0.x + b0.x;
    o0.y = (v0.y - mu) * inv * g0.y + b0.y;
    o0.z = (v0.z - mu) * inv * g0.z + b0.z;
    o0.w = (v0.w - mu) * inv * g0.w + b0.w;
    o1.x = (v1.x - mu) * inv * g1.x + b1.x;
    o1.y = (v1.y - mu) * inv * g1.y + b1.y;
    o1.z = (v1.z - mu) * inv * g1.z + b1.z;
    o1.w = (v1.w - mu) * inv * g1.w + b1.w;
    float* y = out + (size_t)warp * 256 + lane * 8;
    *(float4*)(y)     = o0;
    *(float4*)(y + 4) = o1;
}

// ---------------- host launcher ----------------
extern "C" void kernel_launch(void* const* d_in, const int* in_sizes, int n_in,
                              void* d_out, int out_size) {
    const float* tgt   = (const float*)d_in[0];
    const float* qpos  = (const float*)d_in[1];
    const float* refp  = (const float*)d_in[2];
    const float* src   = (const float*)d_in[3];
    const float* Wv    = (const float*)d_in[6];
    const float* bv    = (const float*)d_in[7];
    const float* Woff  = (const float*)d_in[8];
    const float* boff  = (const float*)d_in[9];
    const float* Wat   = (const float*)d_in[10];
    const float* bat   = (const float*)d_in[11];
    const float* Wout  = (const float*)d_in[12];
    const float* bout  = (const float*)d_in[13];
    const float* ln1g  = (const float*)d_in[14];
    const float* ln1b  = (const float*)d_in[15];
    const float* W1    = (const float*)d_in[16];
    const float* b1    = (const float*)d_in[17];
    const float* W2    = (const float*)d_in[18];
    const float* b2    = (const float*)d_in[19];
    const float* ln3g  = (const float*)d_in[20];
    const float* ln3b  = (const float*)d_in[21];
    float* out = (float*)d_out;

    float *p_q, *p_val, *p_off, *p_att, *p_smp, *p_x, *p_h;
    cudaGetSymbolAddress((void**)&p_q,   g_q);
    cudaGetSymbolAddress((void**)&p_val, g_val);
    cudaGetSymbolAddress((void**)&p_off, g_off);
    cudaGetSymbolAddress((void**)&p_att, g_att);
    cudaGetSymbolAddress((void**)&p_smp, g_smp);
    cudaGetSymbolAddress((void**)&p_x,   g_x);
    cudaGetSymbolAddress((void**)&p_h,   g_h);

    // 1. q = tgt + query_pos
    {
        int n4 = ROWS * DM / 4;
        add_kernel<<<(n4 + 255) / 256, 256>>>(tgt, qpos, p_q, n4);
    }
    // 2. value = src @ Wv + bv        (43520 x 256 x 256)
    sgemm_kernel<0><<<dim3(DM / BN, MVAL / BM), 256>>>(src, Wv, bv, nullptr, p_val, MVAL, DM, DM);
    // 3. off = q @ Woff + boff        (16384 x 256 x 256)
    sgemm_kernel<0><<<dim3(DM / BN, ROWS / BM), 256>>>(p_q, Woff, boff, nullptr, p_off, ROWS, DM, DM);
    // 4. attn logits = q @ Wat + bat  (16384 x 128 x 256)
    sgemm_kernel<0><<<dim3(128 / BN, ROWS / BM), 256>>>(p_q, Wat, bat, nullptr, p_att, ROWS, 128, DM);
    // 5. deformable sampling -> g_smp
    {
        int nwarps = ROWS * NHEADS;           // 131072
        sample_kernel<<<nwarps / 8, 256>>>(p_val, p_off, p_att, refp, p_smp);
    }
    // 6. x_pre = smp @ Wout + bout + tgt  (reuse g_q)
    sgemm_kernel<2><<<dim3(DM / BN, ROWS / BM), 256>>>(p_smp, Wout, bout, tgt, p_q, ROWS, DM, DM);
    // 7. x = LN1(x_pre)
    ln_kernel<<<ROWS / 8, 256>>>(p_q, ln1g, ln1b, p_x, ROWS);
    // 8. h = relu(x @ W1 + b1)        (16384 x 1024 x 256)
    sgemm_kernel<1><<<dim3(DFFN / BN, ROWS / BM), 256>>>(p_x, W1, b1, nullptr, p_h, ROWS, DFFN, DM);
    // 9. y_pre = h @ W2 + b2 + x      (16384 x 256 x 1024, reuse g_off)
    sgemm_kernel<2><<<dim3(DM / BN, ROWS / BM), 256>>>(p_h, W2, b2, p_x, p_off, ROWS, DM, DFFN);
    // 10. out = LN3(y_pre)
    ln_kernel<<<ROWS / 8, 256>>>(p_off, ln3g, ln3b, out, ROWS);
}

// round 6
// speedup vs baseline: 2.9377x; 1.4856x over previous
#include <cuda_runtime.h>
#include <cuda_bf16.h>
#include <math.h>

// ---------------- problem constants ----------------
#define BATCH    2
#define LQ       8192
#define DM       256
#define DFFN     1024
#define NHEADS   8
#define NLEV     4
#define NPTS     4
#define DHEAD    32
#define STOT     21760           // 128*128 + 64*64 + 32*32 + 16*16
#define ROWS     (BATCH*LQ)      // 16384
#define MVAL     (BATCH*STOT)    // 43520

// ---------------- device scratch (allocation-free) ----------------
__device__ float g_q   [ROWS * DM];
__device__ float g_val [MVAL * DM];
__device__ float g_off [ROWS * DM];
__device__ float g_att [ROWS * (NHEADS*NLEV*NPTS)];
__device__ float g_smp [ROWS * DM];
__device__ float g_x   [ROWS * DM];
__device__ float g_h   [ROWS * DFFN];

// ---------------- elementwise add (float4) ----------------
__global__ void add_kernel(const float* __restrict__ a, const float* __restrict__ b,
                           float* __restrict__ o, int n4) {
    int i = blockIdx.x * blockDim.x + threadIdx.x;
    if (i < n4) {
        float4 x = ((const float4*)a)[i];
        float4 y = ((const float4*)b)[i];
        x.x += y.x; x.y += y.y; x.z += y.z; x.w += y.w;
        ((float4*)o)[i] = x;
    }
}

// ---------------- bf16 hi/lo split helpers ----------------
__device__ __forceinline__ void split4(float4 v, unsigned& h0, unsigned& h1,
                                       unsigned& l0, unsigned& l1) {
    __nv_bfloat162 hA = __floats2bfloat162_rn(v.x, v.y);
    __nv_bfloat162 hB = __floats2bfloat162_rn(v.z, v.w);
    float rx = v.x - __bfloat162float(hA.x);
    float ry = v.y - __bfloat162float(hA.y);
    float rz = v.z - __bfloat162float(hB.x);
    float rw = v.w - __bfloat162float(hB.y);
    __nv_bfloat162 lA = __floats2bfloat162_rn(rx, ry);
    __nv_bfloat162 lB = __floats2bfloat162_rn(rz, rw);
    h0 = *(unsigned*)&hA; h1 = *(unsigned*)&hB;
    l0 = *(unsigned*)&lA; l1 = *(unsigned*)&lB;
}

__device__ __forceinline__ void ldsm4(unsigned* r, unsigned addr) {
    asm volatile("ldmatrix.sync.aligned.m8n8.x4.shared.b16 {%0,%1,%2,%3}, [%4];"
                 : "=r"(r[0]), "=r"(r[1]), "=r"(r[2]), "=r"(r[3]) : "r"(addr));
}
__device__ __forceinline__ void ldsm4t(unsigned* r, unsigned addr) {
    asm volatile("ldmatrix.sync.aligned.m8n8.x4.trans.shared.b16 {%0,%1,%2,%3}, [%4];"
                 : "=r"(r[0]), "=r"(r[1]), "=r"(r[2]), "=r"(r[3]) : "r"(addr));
}
__device__ __forceinline__ void mma16816(float* c, const unsigned* a, unsigned b0, unsigned b1) {
    asm volatile("mma.sync.aligned.m16n8k16.row.col.f32.bf16.bf16.f32 "
                 "{%0,%1,%2,%3}, {%4,%5,%6,%7}, {%8,%9}, {%0,%1,%2,%3};"
                 : "+f"(c[0]), "+f"(c[1]), "+f"(c[2]), "+f"(c[3])
                 : "r"(a[0]), "r"(a[1]), "r"(a[2]), "r"(a[3]), "r"(b0), "r"(b1));
}

// ---------------- tensor-core GEMM (bf16 hi/lo 3-term, ~fp32 accuracy) ----------------
// C = op(A@B + bias [+ res]); A:(M,K) row-major, B:(K,N) row-major.
// Block 128x128x32, 8 warps, warp tile 64x32. M%128==0, N%128==0, K%32==0.
#define APITCH 40     // 32 + 8 pad (bf16 elems) -> conflict-free ldmatrix
#define BPITCH 136    // 128 + 8 pad

template<int MODE>
__global__ __launch_bounds__(256)
void hgemm_kernel(const float* __restrict__ A, const float* __restrict__ B,
                  const float* __restrict__ bias, const float* __restrict__ res,
                  float* __restrict__ C, int M, int N, int K) {
    __shared__ unsigned short Ah[128 * APITCH];
    __shared__ unsigned short Al[128 * APITCH];
    __shared__ unsigned short Bh[32 * BPITCH];
    __shared__ unsigned short Bl[32 * BPITCH];

    const int tid  = threadIdx.x;
    const int lane = tid & 31;
    const int wid  = tid >> 5;
    const int wm   = wid >> 2;        // 0..1  (64-row slab)
    const int wn   = wid & 3;         // 0..3  (32-col slab)
    const int bm0  = blockIdx.y * 128;
    const int bn0  = blockIdx.x * 128;

    // global loader mapping
    const int arow = tid >> 1, acol0 = (tid & 1) * 16;   // A: 128 rows x 32 cols
    const int brow = tid >> 3, bcol0 = (tid & 7) * 16;   // B: 32 rows x 128 cols
    const float* Ap = A + (size_t)(bm0 + arow) * K + acol0;
    const float* Bp = B + (size_t)brow * N + bn0 + bcol0;

    // smem store pointers (16B aligned, verified)
    uint4* stAh = (uint4*)(Ah + arow * APITCH + acol0);
    uint4* stAl = (uint4*)(Al + arow * APITCH + acol0);
    uint4* stBh = (uint4*)(Bh + brow * BPITCH + bcol0);
    uint4* stBl = (uint4*)(Bl + brow * BPITCH + bcol0);

    // ldmatrix lane addressing
    const int lrow  = lane & 15;
    const int lcol8 = (lane >> 4) * 8;
    const unsigned sAh = (unsigned)__cvta_generic_to_shared(Ah) +
                         ((wm * 64 + lrow) * APITCH + lcol8) * 2;
    const unsigned sAl = (unsigned)__cvta_generic_to_shared(Al) +
                         ((wm * 64 + lrow) * APITCH + lcol8) * 2;
    const unsigned sBh = (unsigned)__cvta_generic_to_shared(Bh) +
                         (lrow * BPITCH + wn * 32 + lcol8) * 2;
    const unsigned sBl = (unsigned)__cvta_generic_to_shared(Bl) +
                         (lrow * BPITCH + wn * 32 + lcol8) * 2;

    float acc[4][4][4];
#pragma unroll
    for (int mi = 0; mi < 4; mi++)
#pragma unroll
        for (int ni = 0; ni < 4; ni++)
#pragma unroll
            for (int c = 0; c < 4; c++) acc[mi][ni][c] = 0.f;

    float4 af[4], bf[4];
#pragma unroll
    for (int j = 0; j < 4; j++) {
        af[j] = *(const float4*)(Ap + 4 * j);
        bf[j] = *(const float4*)(Bp + 4 * j);
    }

    const int T = K / 32;
    for (int t = 0; t < T; t++) {
        if (t > 0) __syncthreads();
        // convert + store current tile
        {
            unsigned h[8], l[8];
#pragma unroll
            for (int j = 0; j < 4; j++) split4(af[j], h[2*j], h[2*j+1], l[2*j], l[2*j+1]);
            stAh[0] = make_uint4(h[0], h[1], h[2], h[3]);
            stAh[1] = make_uint4(h[4], h[5], h[6], h[7]);
            stAl[0] = make_uint4(l[0], l[1], l[2], l[3]);
            stAl[1] = make_uint4(l[4], l[5], l[6], l[7]);
#pragma unroll
            for (int j = 0; j < 4; j++) split4(bf[j], h[2*j], h[2*j+1], l[2*j], l[2*j+1]);
            stBh[0] = make_uint4(h[0], h[1], h[2], h[3]);
            stBh[1] = make_uint4(h[4], h[5], h[6], h[7]);
            stBl[0] = make_uint4(l[0], l[1], l[2], l[3]);
            stBl[1] = make_uint4(l[4], l[5], l[6], l[7]);
        }
        __syncthreads();
        // prefetch next tile (LDG issued before the mma block)
        if (t + 1 < T) {
#pragma unroll
            for (int j = 0; j < 4; j++) {
                af[j] = *(const float4*)(Ap + (t + 1) * 32 + 4 * j);
                bf[j] = *(const float4*)(Bp + (size_t)(t + 1) * 32 * N + 4 * j);
            }
        }
        // compute: 2 k-chunks of 16
#pragma unroll
        for (int kc = 0; kc < 2; kc++) {
            unsigned Afh[4][4], Afl[4][4];
#pragma unroll
            for (int mi = 0; mi < 4; mi++) {
                ldsm4(Afh[mi], sAh + (mi * 16 * APITCH + kc * 16) * 2);
                ldsm4(Afl[mi], sAl + (mi * 16 * APITCH + kc * 16) * 2);
            }
            unsigned Bfh[2][4], Bfl[2][4];
#pragma unroll
            for (int nc = 0; nc < 2; nc++) {
                ldsm4t(Bfh[nc], sBh + (kc * 16 * BPITCH + nc * 16) * 2);
                ldsm4t(Bfl[nc], sBl + (kc * 16 * BPITCH + nc * 16) * 2);
            }
#pragma unroll
            for (int mi = 0; mi < 4; mi++)
#pragma unroll
                for (int ni = 0; ni < 4; ni++) {
                    const int nc = ni >> 1, sub = (ni & 1) * 2;
                    unsigned bh0 = Bfh[nc][sub], bh1 = Bfh[nc][sub + 1];
                    unsigned bl0 = Bfl[nc][sub], bl1 = Bfl[nc][sub + 1];
                    mma16816(acc[mi][ni], Afh[mi], bh0, bh1);   // hi*hi
                    mma16816(acc[mi][ni], Afh[mi], bl0, bl1);   // hi*lo
                    mma16816(acc[mi][ni], Afl[mi], bh0, bh1);   // lo*hi
                }
        }
        __syncthreads();
    }

    // epilogue: lane owns (row = base + t/4 [+8], col = base + (t%4)*2 .. +1)
    const int r0 = bm0 + wm * 64 + (lane >> 2);
    const int c0 = bn0 + wn * 32 + (lane & 3) * 2;
#pragma unroll
    for (int mi = 0; mi < 4; mi++) {
#pragma unroll
        for (int ni = 0; ni < 4; ni++) {
            const int col = c0 + ni * 8;
            float2 bb = *(const float2*)&bias[col];
#pragma unroll
            for (int half = 0; half < 2; half++) {
                const int row = r0 + mi * 16 + half * 8;
                const size_t off = (size_t)row * N + col;
                float2 v;
                v.x = acc[mi][ni][half * 2 + 0] + bb.x;
                v.y = acc[mi][ni][half * 2 + 1] + bb.y;
                if (MODE == 1) { v.x = fmaxf(v.x, 0.f); v.y = fmaxf(v.y, 0.f); }
                if (MODE == 2) {
                    float2 r = *(const float2*)&res[off];
                    v.x += r.x; v.y += r.y;
                }
                *(float2*)&C[off] = v;
            }
        }
    }
}

// ---------------- deformable sampling ----------------
// one warp per (b, q, h); lane = head-dim channel
__global__ void sample_kernel(const float* __restrict__ value,   // (B*S, 256)
                              const float* __restrict__ offp_g,  // (ROWS, 256)
                              const float* __restrict__ attn_g,  // (ROWS, 128) logits
                              const float* __restrict__ refp,    // (B, LQ, 4, 2)
                              float* __restrict__ out)           // (ROWS, 256)
{
    const int gw   = blockIdx.x * (blockDim.x >> 5) + (threadIdx.x >> 5);
    const int lane = threadIdx.x & 31;
    const int h    = gw & 7;
    const int row  = gw >> 3;            // b*LQ + q
    if (row >= ROWS) return;
    const int b = row / LQ;

    const int HH[NLEV]    = {128, 64, 32, 16};
    const int WW[NLEV]    = {128, 64, 32, 16};
    const int START[NLEV] = {0, 16384, 20480, 21504};

    const float* ap = attn_g + (size_t)row * 128 + h * 16;
    float lg[16];
#pragma unroll
    for (int j = 0; j < 16; j++) lg[j] = ap[j];
    float mx = lg[0];
#pragma unroll
    for (int j = 1; j < 16; j++) mx = fmaxf(mx, lg[j]);
    float s = 0.f;
#pragma unroll
    for (int j = 0; j < 16; j++) { lg[j] = __expf(lg[j] - mx); s += lg[j]; }
    const float inv = 1.f / s;

    const float* offp = offp_g + (size_t)row * 256 + h * 32;
    const float* rp   = refp + (size_t)row * (NLEV * 2);

    float acc = 0.f;
#pragma unroll
    for (int l = 0; l < NLEV; l++) {
        const int Hl = HH[l], Wl = WW[l];
        const float rx = rp[l * 2 + 0] * (float)Wl;
        const float ry = rp[l * 2 + 1] * (float)Hl;
        const float* vbase = value + ((size_t)(b * STOT + START[l])) * 256 + h * 32 + lane;
#pragma unroll
        for (int p = 0; p < NPTS; p++) {
            const float x = rx + offp[l * 8 + p * 2 + 0] - 0.5f;
            const float y = ry + offp[l * 8 + p * 2 + 1] - 0.5f;
            const float x0f = floorf(x), y0f = floorf(y);
            const float wx = x - x0f, wy = y - y0f;
            const int x0 = (int)x0f, y0 = (int)y0f;
            const float aw = lg[l * 4 + p] * inv;

            const float w00 = (1.f - wx) * (1.f - wy) * aw;
            const float w10 = wx * (1.f - wy) * aw;
            const float w01 = (1.f - wx) * wy * aw;
            const float w11 = wx * wy * aw;

            if (x0     >= 0 && x0     < Wl && y0     >= 0 && y0     < Hl)
                acc += w00 * vbase[(size_t)(y0 * Wl + x0) * 256];
            if (x0 + 1 >= 0 && x0 + 1 < Wl && y0     >= 0 && y0     < Hl)
                acc += w10 * vbase[(size_t)(y0 * Wl + x0 + 1) * 256];
            if (x0     >= 0 && x0     < Wl && y0 + 1 >= 0 && y0 + 1 < Hl)
                acc += w01 * vbase[(size_t)((y0 + 1) * Wl + x0) * 256];
            if (x0 + 1 >= 0 && x0 + 1 < Wl && y0 + 1 >= 0 && y0 + 1 < Hl)
                acc += w11 * vbase[(size_t)((y0 + 1) * Wl + x0 + 1) * 256];
        }
    }
    out[(size_t)row * 256 + h * 32 + lane] = acc;
}

// ---------------- layernorm: warp per 256-elem row ----------------
__global__ void ln_kernel(const float* __restrict__ in, const float* __restrict__ gam,
                          const float* __restrict__ bet, float* __restrict__ out, int rows) {
    const int warp = (blockIdx.x * blockDim.x + threadIdx.x) >> 5;
    const int lane = threadIdx.x & 31;
    if (warp >= rows) return;
    const float* x = in + (size_t)warp * 256 + lane * 8;
    float4 v0 = *(const float4*)(x);
    float4 v1 = *(const float4*)(x + 4);
    float s  = v0.x + v0.y + v0.z + v0.w + v1.x + v1.y + v1.z + v1.w;
    float ss = v0.x*v0.x + v0.y*v0.y + v0.z*v0.z + v0.w*v0.w
             + v1.x*v1.x + v1.y*v1.y + v1.z*v1.z + v1.w*v1.w;
#pragma unroll
    for (int o = 16; o > 0; o >>= 1) {
        s  += __shfl_xor_sync(0xffffffffu, s,  o);
        ss += __shfl_xor_sync(0xffffffffu, ss, o);
    }
    const float mu  = s * (1.f / 256.f);
    const float var = ss * (1.f / 256.f) - mu * mu;
    const float inv = rsqrtf(var + 1e-5f);

    float4 g0 = *(const float4*)(gam + lane * 8);
    float4 g1 = *(const float4*)(gam + lane * 8 + 4);
    float4 b0 = *(const float4*)(bet + lane * 8);
    float4 b1 = *(const float4*)(bet + lane * 8 + 4);
    float4 o0, o1;
    o0.x = (v0.x - mu) * inv * g0.x + b0.x;
    o0.y = (v0.y - mu) * inv * g0.y + b0.y;
    o0.z = (v0.z - mu) * inv * g0.z + b0.z;
    o0.w = (v0.w - mu) * inv * g0.w + b0.w;
    o1.x = (v1.x - mu) * inv * g1.x + b1.x;
    o1.y = (v1.y - mu) * inv * g1.y + b1.y;
    o1.z = (v1.z - mu) * inv * g1.z + b1.z;
    o1.w = (v1.w - mu) * inv * g1.w + b1.w;
    float* y = out + (size_t)warp * 256 + lane * 8;
    *(float4*)(y)     = o0;
    *(float4*)(y + 4) = o1;
}

// ---------------- host launcher ----------------
extern "C" void kernel_launch(void* const* d_in, const int* in_sizes, int n_in,
                              void* d_out, int out_size) {
    const float* tgt   = (const float*)d_in[0];
    const float* qpos  = (const float*)d_in[1];
    const float* refp  = (const float*)d_in[2];
    const float* src   = (const float*)d_in[3];
    const float* Wv    = (const float*)d_in[6];
    const float* bv    = (const float*)d_in[7];
    const float* Woff  = (const float*)d_in[8];
    const float* boff  = (const float*)d_in[9];
    const float* Wat   = (const float*)d_in[10];
    const float* bat   = (const float*)d_in[11];
    const float* Wout  = (const float*)d_in[12];
    const float* bout  = (const float*)d_in[13];
    const float* ln1g  = (const float*)d_in[14];
    const float* ln1b  = (const float*)d_in[15];
    const float* W1    = (const float*)d_in[16];
    const float* b1    = (const float*)d_in[17];
    const float* W2    = (const float*)d_in[18];
    const float* b2    = (const float*)d_in[19];
    const float* ln3g  = (const float*)d_in[20];
    const float* ln3b  = (const float*)d_in[21];
    float* out = (float*)d_out;

    float *p_q, *p_val, *p_off, *p_att, *p_smp, *p_x, *p_h;
    cudaGetSymbolAddress((void**)&p_q,   g_q);
    cudaGetSymbolAddress((void**)&p_val, g_val);
    cudaGetSymbolAddress((void**)&p_off, g_off);
    cudaGetSymbolAddress((void**)&p_att, g_att);
    cudaGetSymbolAddress((void**)&p_smp, g_smp);
    cudaGetSymbolAddress((void**)&p_x,   g_x);
    cudaGetSymbolAddress((void**)&p_h,   g_h);

    // 1. q = tgt + query_pos
    {
        int n4 = ROWS * DM / 4;
        add_kernel<<<(n4 + 255) / 256, 256>>>(tgt, qpos, p_q, n4);
    }
    // 2. value = src @ Wv + bv        (43520 x 256 x 256)
    hgemm_kernel<0><<<dim3(DM / 128, MVAL / 128), 256>>>(src, Wv, bv, nullptr, p_val, MVAL, DM, DM);
    // 3. off = q @ Woff + boff        (16384 x 256 x 256)
    hgemm_kernel<0><<<dim3(DM / 128, ROWS / 128), 256>>>(p_q, Woff, boff, nullptr, p_off, ROWS, DM, DM);
    // 4. attn logits = q @ Wat + bat  (16384 x 128 x 256)
    hgemm_kernel<0><<<dim3(128 / 128, ROWS / 128), 256>>>(p_q, Wat, bat, nullptr, p_att, ROWS, 128, DM);
    // 5. deformable sampling -> g_smp
    {
        int nwarps = ROWS * NHEADS;           // 131072
        sample_kernel<<<nwarps / 8, 256>>>(p_val, p_off, p_att, refp, p_smp);
    }
    // 6. x_pre = smp @ Wout + bout + tgt  (reuse g_q)
    hgemm_kernel<2><<<dim3(DM / 128, ROWS / 128), 256>>>(p_smp, Wout, bout, tgt, p_q, ROWS, DM, DM);
    // 7. x = LN1(x_pre)
    ln_kernel<<<ROWS / 8, 256>>>(p_q, ln1g, ln1b, p_x, ROWS);
    // 8. h = relu(x @ W1 + b1)        (16384 x 1024 x 256)
    hgemm_kernel<1><<<dim3(DFFN / 128, ROWS / 128), 256>>>(p_x, W1, b1, nullptr, p_h, ROWS, DFFN, DM);
    // 9. y_pre = h @ W2 + b2 + x      (16384 x 256 x 1024, reuse g_off)
    hgemm_kernel<2><<<dim3(DM / 128, ROWS / 128), 256>>>(p_h, W2, b2, p_x, p_off, ROWS, DM, DFFN);
    // 10. out = LN3(y_pre)
    ln_kernel<<<ROWS / 8, 256>>>(p_off, ln3g, ln3b, out, ROWS);
}